// round 7
// baseline (speedup 1.0000x reference)
#include <cuda_runtime.h>

#define BB 4
#define NN 8
#define HH 48
#define WW 48
#define HW (HH*WW)        /* 2304 */
#define TH 6
#define SMH (TH+6)
#define SMW (WW+6)
#define OUTM_ELEMS (BB*3*HW)   /* 27648 */

// Zero the pred_img accumulation region (float4 stores).
__global__ void zero_kernel(float4* __restrict__ p)
{
    int i = blockIdx.x * blockDim.x + threadIdx.x;
    if (i < OUTM_ELEMS/4) p[i] = make_float4(0.f, 0.f, 0.f, 0.f);
}

// Fused rank-1 kernel-prediction apply + n-mean accumulation.
// One RGB channel t per block (gridDim.x = tiles*3) to shorten threads and
// raise occupancy. Patch values are consumed row-by-row straight from SMEM.
//
// pred_img_i[b,n,t,h,w] = 0.25 * sum_s W[b,n,s,t] * S_{K(s)},  K(s)=7,5,3,1
// S_K = sum_c sum_k c1[cur+k,c,t] * sum_l c2[cur+l,c,t] * F[c, h+k-3, w+l-3]
__global__ __launch_bounds__(WW*TH, 3)
void kpn_kernel(const float* __restrict__ frames,
                const float* __restrict__ core,
                const float* __restrict__ kw,
                float* __restrict__ out_i,
                float* __restrict__ out_m)
{
    const int tile = blockIdx.x / 3;
    const int t    = blockIdx.x - tile*3;
    const int n    = blockIdx.y;
    const int b    = blockIdx.z;
    const int h0   = tile * TH;

    __shared__ float sF[4][SMH][SMW];   // 10368 B

    const int tid = threadIdx.x;

    // Cooperative load of the frames tile (zero-padded halo of 3)
    const float* fbase = frames + ((size_t)(b*NN + n)) * 4 * HW;
    for (int idx = tid; idx < 4*SMH*SMW; idx += WW*TH) {
        int c   = idx / (SMH*SMW);
        int rem = idx - c*(SMH*SMW);
        int i   = rem / SMW;
        int j   = rem - i*SMW;
        int hh  = h0 + i - 3;
        int wp  = j - 3;
        float v = 0.f;
        if ((unsigned)hh < HH && (unsigned)wp < WW)
            v = fbase[c*HW + hh*WW + wp];
        sF[c][i][j] = v;
    }
    __syncthreads();

    const int w   = tid % WW;
    const int ti  = tid / WW;            // 0..TH-1
    const int h   = h0 + ti;
    const int pix = h*WW + w;

    // core channels: ch = ((q*4 + c)*3 + t), stride HW. q<16 -> c1, q>=16 -> c2.
    const float* cbase = core + (size_t)b*3072*HW + (size_t)n*384*HW
                              + (size_t)t*HW + pix;

    float acc0 = 0.f, acc1 = 0.f, acc2 = 0.f, acc3 = 0.f;  // K1,K3,K5,K7

    #pragma unroll 1
    for (int c = 0; c < 4; c++) {
        // Batch all 32 channel loads for this (c) up front -> max MLP
        float c1v[16], c2v[16];
        #pragma unroll
        for (int q = 0; q < 16; q++) {
            c1v[q] = cbase[(size_t)(((q     )*4 + c)*3) * HW];
            c2v[q] = cbase[(size_t)(((16 + q)*4 + c)*3) * HW];
        }

        // Walk the 7 patch rows once; each row feeds K7 always,
        // K5 for i in [1,5], K3 for i in [2,4], K1 at i==3.
        #pragma unroll
        for (int i = 0; i < 7; i++) {
            float v[7];
            #pragma unroll
            for (int l = 0; l < 7; l++)
                v[l] = sF[c][ti + i][w + l];

            // K7: cur=9, pad=0
            float rs7 = 0.f;
            #pragma unroll
            for (int l = 0; l < 7; l++)
                rs7 += c2v[9 + l] * v[l];
            acc3 += c1v[9 + i] * rs7;

            // K5: cur=4, pad=1 (rows 1..5)
            if (i >= 1 && i <= 5) {
                float rs5 = 0.f;
                #pragma unroll
                for (int l = 0; l < 5; l++)
                    rs5 += c2v[4 + l] * v[1 + l];
                acc2 += c1v[4 + (i - 1)] * rs5;
            }
            // K3: cur=1, pad=2 (rows 2..4)
            if (i >= 2 && i <= 4) {
                float rs3 = c2v[1]*v[2] + c2v[2]*v[3] + c2v[3]*v[4];
                acc1 += c1v[1 + (i - 2)] * rs3;
            }
            // K1: cur=0, pad=3 (row 3)
            if (i == 3)
                acc0 += c1v[0] * (c2v[0] * v[3]);
        }
    }

    // kernel_weight[b][n][s][t][h][w]; s=0 pairs with K=7 (stack order KS[::-1])
    const float* wb = kw + ((size_t)(b*NN + n)) * 4 * 3 * HW + (size_t)t*HW + pix;
    float r = wb[0*3*HW] * acc3
            + wb[1*3*HW] * acc2
            + wb[2*3*HW] * acc1
            + wb[3*3*HW] * acc0;

    out_i[((size_t)(b*NN + n)) * 3 * HW + (size_t)t*HW + pix] = 0.25f * r;
    atomicAdd(out_m + (size_t)b * 3 * HW + (size_t)t*HW + pix, 0.03125f * r);
}

extern "C" void kernel_launch(void* const* d_in, const int* in_sizes, int n_in,
                              void* d_out, int out_size)
{
    const float* frames = (const float*)d_in[0];
    const float* core   = (const float*)d_in[1];
    const float* kw     = (const float*)d_in[2];

    float* out   = (float*)d_out;
    float* out_i = out;                    // pred_img_i: (4,8,3,48,48) = 221184
    float* out_m = out + BB*NN*3*HW;       // pred_img:   (4,3,48,48)   =  27648

    zero_kernel<<<(OUTM_ELEMS/4 + 255)/256, 256>>>((float4*)out_m);

    dim3 grid((HH/TH)*3, NN, BB);          // 24 x 8 x 4 = 768 blocks
    kpn_kernel<<<grid, WW*TH>>>(frames, core, kw, out_i, out_m);
}